// round 8
// baseline (speedup 1.0000x reference)
#include <cuda_runtime.h>
#include <cuda_bf16.h>
#include <math.h>

// TorchGemma4VisionPooler: 2x2 average pool over a dense 64x64 patch grid,
// scaled by sqrt(H). B=8, S=4096, H=1152, OUT_LEN=1024.
//
// R6 design (third submit; prior two attempts hit infra GPU-acquisition
// timeouts, never executed):
// exact-factorization persistent kernel. total_pairs = 1,179,648 =
// 294,912 x 4, so 1152 blocks x 256 threads run EXACTLY 4 grid-stride
// iterations each — no bounds check, no straggler tail. Stride 294,912 is
// divisible by C4_=288 (quotient 1024 = 2*512), so c/op/s0 are iteration-
// invariant and only the batch index advances by 2: all index math hoisted,
// loop body = 8 streaming LDG.128 + 2 STG.128 + 2 pointer bumps.
// 1152 <= 1184 resident CTAs -> still a single wave. DRAM-bound (189 MB).

static constexpr int B_ = 8;
static constexpr int GRID_ = 64;
static constexpr int S_ = GRID_ * GRID_;     // 4096
static constexpr int H_ = 1152;
static constexpr int C4_ = H_ / 4;           // 288 float4 per row
static constexpr int OG_ = 32;               // output grid 32x32
static constexpr int L_ = OG_ * OG_;         // 1024
static constexpr int OUT_ELEMS_ = B_ * L_ * H_;  // 9437184
static constexpr int MASK_ELEMS_ = B_ * L_;      // 8192

static constexpr int THREADS_ = 256;
static constexpr int BLOCKS_ = 1152;                 // one resident wave
static constexpr int STRIDE_ = THREADS_ * BLOCKS_;   // 294912 = total_pairs/4
static constexpr int ITERS_ = 4;

// per-iteration pointer advance: batch index b += 2
static constexpr size_t IN_STEP_  = (size_t)2 * S_ * C4_;  // float4s
static constexpr size_t OUT_STEP_ = (size_t)2 * L_ * C4_;  // float4s

// sqrt(1152)/4
static constexpr float SCALE_ = 8.485281374238570f;

__global__ __launch_bounds__(THREADS_, 8)
void pool2x2_exact_kernel(const float4* __restrict__ in,
                          float4* __restrict__ out,
                          float* __restrict__ mask_tail,
                          int write_mask) {
    int tid0 = blockIdx.x * THREADS_ + threadIdx.x;   // [0, 294912)

    // fused mask write: first MASK_ELEMS_ threads each write one 1.0f
    if (write_mask && tid0 < MASK_ELEMS_) {
        mask_tail[tid0] = 1.0f;
    }

    // hoisted index math (invariant across all 4 iterations except b += 2)
    int c  = tid0 % C4_;
    int r  = tid0 / C4_;          // [0, 1024)
    int op = r % (L_ / 2);        // output-pair index [0, 512)
    int b0 = r / (L_ / 2);        // starting batch: 0 or 1

    int o0 = op * 2;              // even output index; o1 = o0+1
    int ox = o0 & (OG_ - 1);
    int oy = o0 >> 5;
    int s0 = (oy * 2) * GRID_ + ox * 2;   // top-left source patch

    const float4* inp  = in  + ((size_t)b0 * S_ + s0) * C4_ + c;
    float4*       outp = out + ((size_t)b0 * L_ + o0) * C4_ + c;

    #pragma unroll 1
    for (int it = 0; it < ITERS_; it++) {
        // 8 independent streaming loads, front-batched
        float4 r0 = __ldcs(inp + 0 * C4_);
        float4 r1 = __ldcs(inp + 1 * C4_);
        float4 r2 = __ldcs(inp + 2 * C4_);
        float4 r3 = __ldcs(inp + 3 * C4_);
        float4 r4 = __ldcs(inp + (size_t)(GRID_ + 0) * C4_);
        float4 r5 = __ldcs(inp + (size_t)(GRID_ + 1) * C4_);
        float4 r6 = __ldcs(inp + (size_t)(GRID_ + 2) * C4_);
        float4 r7 = __ldcs(inp + (size_t)(GRID_ + 3) * C4_);

        float4 w0, w1;
        w0.x = ((r0.x + r1.x) + (r4.x + r5.x)) * SCALE_;
        w0.y = ((r0.y + r1.y) + (r4.y + r5.y)) * SCALE_;
        w0.z = ((r0.z + r1.z) + (r4.z + r5.z)) * SCALE_;
        w0.w = ((r0.w + r1.w) + (r4.w + r5.w)) * SCALE_;
        w1.x = ((r2.x + r3.x) + (r6.x + r7.x)) * SCALE_;
        w1.y = ((r2.y + r3.y) + (r6.y + r7.y)) * SCALE_;
        w1.z = ((r2.z + r3.z) + (r6.z + r7.z)) * SCALE_;
        w1.w = ((r2.w + r3.w) + (r6.w + r7.w)) * SCALE_;

        __stcs(outp, w0);
        __stcs(outp + C4_, w1);

        inp  += IN_STEP_;
        outp += OUT_STEP_;
    }
}

extern "C" void kernel_launch(void* const* d_in, const int* in_sizes, int n_in,
                              void* d_out, int out_size) {
    const float4* in = (const float4*)d_in[0];
    float4* out = (float4*)d_out;

    int write_mask = (out_size > OUT_ELEMS_) ? 1 : 0;
    float* mask_tail = (float*)d_out + OUT_ELEMS_;

    pool2x2_exact_kernel<<<BLOCKS_, THREADS_>>>(in, out, mask_tail, write_mask);
}